// round 7
// baseline (speedup 1.0000x reference)
#include <cuda_runtime.h>
#include <math_constants.h>

// Problem dims (fixed by the reference)
#define BB 4
#define TT 2048
#define CC 1024
#define HH 16
#define DD 64
#define BT (BB*TT)      // 8192 rows
#define F3 (3*CC)       // 3072 qkv features

// Scratch (allocation-free rule: __device__ globals)
__device__ float g_qkv[BT * F3];   // 100.7 MB
__device__ float g_att[BT * CC];   // 33.6 MB

// ---------------------------------------------------------------------------
// tf32 helpers: 3-term split (hi*hi + hi*lo + lo*hi) gives ~fp32 accuracy
// ---------------------------------------------------------------------------
__device__ __forceinline__ void split_tf32(float x, unsigned& hi, unsigned& lo) {
    unsigned h; asm("cvt.rna.tf32.f32 %0, %1;" : "=r"(h) : "f"(x));
    float r = x - __uint_as_float(h);
    unsigned l; asm("cvt.rna.tf32.f32 %0, %1;" : "=r"(l) : "f"(r));
    hi = h; lo = l;
}

__device__ __forceinline__ void mma_tf32(float c[4], const unsigned a[4],
                                         unsigned b0, unsigned b1) {
    asm volatile(
        "mma.sync.aligned.m16n8k8.row.col.f32.tf32.tf32.f32 "
        "{%0,%1,%2,%3},{%4,%5,%6,%7},{%8,%9},{%0,%1,%2,%3};"
        : "+f"(c[0]), "+f"(c[1]), "+f"(c[2]), "+f"(c[3])
        : "r"(a[0]), "r"(a[1]), "r"(a[2]), "r"(a[3]), "r"(b0), "r"(b1));
}

// ---------------------------------------------------------------------------
// Tensor-core GEMM (NT): C[m][n] = sum_k A[m][k] * W[n][k]
// Block 128x128, BK=16, 256 threads = 8 warps (2m x 4n), warp tile 64x32.
// hi/lo PRE-SPLIT in smem (loader does cvt once); register-staged double buffer.
// ---------------------------------------------------------------------------
#define APITCH 20   // 16 data + 4 pad floats; (lr*20+lc) mod 32 all-distinct

__global__ void __launch_bounds__(256, 2) gemm_nt_tc_kernel(
    const float* __restrict__ A, const float* __restrict__ W,
    float* __restrict__ C, int M, int N, int K)
{
    __shared__ float Ah[128 * APITCH], Al[128 * APITCH];
    __shared__ float Bh[128 * APITCH], Bl[128 * APITCH];

    const int tid    = threadIdx.x;
    const int lane   = tid & 31;
    const int warp   = tid >> 5;
    const int warp_m = warp >> 2;          // 0..1 -> 64-row slab
    const int warp_n = warp & 3;           // 0..3 -> 32-col slab
    const int lr     = lane >> 2;          // 0..7
    const int lc     = lane & 3;           // 0..3
    const int m0     = blockIdx.y * 128;
    const int n0     = blockIdx.x * 128;

    const int ldr = tid >> 2;              // 0..63 loader row
    const int ldk = (tid & 3) << 2;        // k sub-offset

    float acc[4][4][4];
    #pragma unroll
    for (int i = 0; i < 4; i++)
        #pragma unroll
        for (int j = 0; j < 4; j++)
            #pragma unroll
            for (int f = 0; f < 4; f++) acc[i][j][f] = 0.f;

    float4 ra0, ra1, rb0, rb1;             // register-staged next tile
    auto ldg_tile = [&](int k0) {
        ra0 = *(const float4*)(A + (size_t)(m0 + ldr)      * K + k0 + ldk);
        ra1 = *(const float4*)(A + (size_t)(m0 + ldr + 64) * K + k0 + ldk);
        rb0 = *(const float4*)(W + (size_t)(n0 + ldr)      * K + k0 + ldk);
        rb1 = *(const float4*)(W + (size_t)(n0 + ldr + 64) * K + k0 + ldk);
    };
    auto sts_split = [&]() {
        const float* pa[2] = { (const float*)&ra0, (const float*)&ra1 };
        const float* pb[2] = { (const float*)&rb0, (const float*)&rb1 };
        #pragma unroll
        for (int it = 0; it < 2; it++) {
            int row = ldr + it * 64;
            #pragma unroll
            for (int j = 0; j < 4; j++) {
                unsigned hi, lo;
                split_tf32(pa[it][j], hi, lo);
                Ah[row * APITCH + ldk + j] = __uint_as_float(hi);
                Al[row * APITCH + ldk + j] = __uint_as_float(lo);
                split_tf32(pb[it][j], hi, lo);
                Bh[row * APITCH + ldk + j] = __uint_as_float(hi);
                Bl[row * APITCH + ldk + j] = __uint_as_float(lo);
            }
        }
    };

    const int KT = K >> 4;
    ldg_tile(0);

    for (int kt = 0; kt < KT; kt++) {
        sts_split();
        __syncthreads();
        if (kt + 1 < KT) ldg_tile((kt + 1) << 4);   // overlap with compute

        #pragma unroll
        for (int k8 = 0; k8 < 16; k8 += 8) {
            unsigned ah[4][4], al[4][4];
            #pragma unroll
            for (int mt = 0; mt < 4; mt++) {
                int ab = (warp_m * 64 + mt * 16 + lr) * APITCH + k8 + lc;
                ah[mt][0] = __float_as_uint(Ah[ab]);
                ah[mt][1] = __float_as_uint(Ah[ab + 8 * APITCH]);
                ah[mt][2] = __float_as_uint(Ah[ab + 4]);
                ah[mt][3] = __float_as_uint(Ah[ab + 8 * APITCH + 4]);
                al[mt][0] = __float_as_uint(Al[ab]);
                al[mt][1] = __float_as_uint(Al[ab + 8 * APITCH]);
                al[mt][2] = __float_as_uint(Al[ab + 4]);
                al[mt][3] = __float_as_uint(Al[ab + 8 * APITCH + 4]);
            }
            #pragma unroll
            for (int nt = 0; nt < 4; nt++) {
                int bb = (warp_n * 32 + nt * 8 + lr) * APITCH + k8 + lc;
                unsigned bh0 = __float_as_uint(Bh[bb]);
                unsigned bh1 = __float_as_uint(Bh[bb + 4]);
                unsigned bl0 = __float_as_uint(Bl[bb]);
                unsigned bl1 = __float_as_uint(Bl[bb + 4]);
                #pragma unroll
                for (int mt = 0; mt < 4; mt++) {
                    mma_tf32(acc[mt][nt], ah[mt], bh0, bh1);
                    mma_tf32(acc[mt][nt], ah[mt], bl0, bl1);
                    mma_tf32(acc[mt][nt], al[mt], bh0, bh1);
                }
            }
        }
        __syncthreads();
    }

    #pragma unroll
    for (int mt = 0; mt < 4; mt++) {
        #pragma unroll
        for (int nt = 0; nt < 4; nt++) {
            int r  = m0 + warp_m * 64 + mt * 16 + lr;
            int cc = n0 + warp_n * 32 + nt * 8 + 2 * lc;
            *(float2*)(C + (size_t)r * N + cc)       = make_float2(acc[mt][nt][0], acc[mt][nt][1]);
            *(float2*)(C + (size_t)(r + 8) * N + cc) = make_float2(acc[mt][nt][2], acc[mt][nt][3]);
        }
    }
}

// ---------------------------------------------------------------------------
// Flash attention (causal) on tensor cores, 3-term tf32 split for S and P@V.
// Block = one (b,h) x 64 query rows. BN=64 keys/tile, D=64.
// 8 warps: warp_m = warp&3 (16 q-rows each), warp_n = warp>>2 (32-key half).
// S per warp: m16 x n32 (4 n-tiles). O partial per warp: m16 x n64 (8 n-tiles),
// accumulated over the warp's key half; halves summed in the epilogue.
// ---------------------------------------------------------------------------
#define PCH 68   // (lr*68+lc) mod 32 all-distinct -> conflict-free frag loads
#define ATT_FLOATS (7 * 64 * PCH + 256)
#define ATT_SMEM (ATT_FLOATS * 4)

__global__ void __launch_bounds__(256) attn_kernel(
    const float* __restrict__ qkv, float* __restrict__ att)
{
    extern __shared__ float smem[];
    float* Qh  = smem;                  // [64][PCH] hi(Q * 0.125)
    float* Ql  = Qh  + 64 * PCH;
    float* Kh  = Ql  + 64 * PCH;        // [key][d]
    float* Kl  = Kh  + 64 * PCH;
    float* Vth = Kl  + 64 * PCH;        // [d][key]  (transposed)
    float* Vtl = Vth + 64 * PCH;
    float* Ps  = Vtl + 64 * PCH;        // [q][key] softmax weights (fp32)
    float* red0 = Ps + 64 * PCH;        // [2][64] row max partials
    float* red1 = red0 + 128;           // [2][64] row sum partials
    float* Obuf = Kh;                   // epilogue reuse of K region

    const int tid    = threadIdx.x;
    const int lane   = tid & 31;
    const int warp   = tid >> 5;
    const int warp_m = warp & 3;        // q-row slab (16 rows)
    const int warp_n = warp >> 2;       // key half (32 keys)
    const int lr     = lane >> 2;
    const int lc     = lane & 3;
    const int bh     = blockIdx.y;
    const int b      = bh >> 4;
    const int h      = bh & 15;
    const int q0     = blockIdx.x * 64;

    const int row0 = warp_m * 16 + lr;  // q-local rows this thread owns
    const int row1 = row0 + 8;

    const float* qbase = qkv + (size_t)(b*TT + q0) * F3 + h*DD;
    const float* kbase = qkv + (size_t)(b*TT) * F3 + CC   + h*DD;
    const float* vbase = qkv + (size_t)(b*TT) * F3 + 2*CC + h*DD;

    // Load Q tile (scaled by 1/sqrt(D)), pre-split hi/lo
    {
        const float scale = 0.125f;
        #pragma unroll
        for (int it = 0; it < 4; it++) {
            int fi = tid + it * 256;
            int r  = fi >> 4;
            int d0 = (fi & 15) << 2;
            float4 v = *(const float4*)(qbase + (size_t)r * F3 + d0);
            float vv[4] = { v.x*scale, v.y*scale, v.z*scale, v.w*scale };
            #pragma unroll
            for (int j = 0; j < 4; j++) {
                unsigned hi, lo; split_tf32(vv[j], hi, lo);
                Qh[r * PCH + d0 + j] = __uint_as_float(hi);
                Ql[r * PCH + d0 + j] = __uint_as_float(lo);
            }
        }
    }

    float m0s = -CUDART_INF_F, m1s = -CUDART_INF_F;
    float l0s = 0.f, l1s = 0.f;
    float oacc[8][4];
    #pragma unroll
    for (int nt = 0; nt < 8; nt++)
        #pragma unroll
        for (int f = 0; f < 4; f++) oacc[nt][f] = 0.f;

    const int nkt = (q0 >> 6) + 1;
    for (int kt = 0; kt < nkt; kt++) {
        const int k0 = kt * 64;

        __syncthreads();   // prior tile fully consumed (K/V/Ps/red)
        // Load K (split) and V (split + transpose)
        #pragma unroll
        for (int it = 0; it < 4; it++) {
            int fi = tid + it * 256;
            int r  = fi >> 4;             // key
            int d0 = (fi & 15) << 2;
            float4 kv = *(const float4*)(kbase + (size_t)(k0 + r) * F3 + d0);
            float kk[4] = { kv.x, kv.y, kv.z, kv.w };
            float4 vv4 = *(const float4*)(vbase + (size_t)(k0 + r) * F3 + d0);
            float vv[4] = { vv4.x, vv4.y, vv4.z, vv4.w };
            #pragma unroll
            for (int j = 0; j < 4; j++) {
                unsigned hi, lo;
                split_tf32(kk[j], hi, lo);
                Kh[r * PCH + d0 + j] = __uint_as_float(hi);
                Kl[r * PCH + d0 + j] = __uint_as_float(lo);
                split_tf32(vv[j], hi, lo);
                Vth[(d0 + j) * PCH + r] = __uint_as_float(hi);
                Vtl[(d0 + j) * PCH + r] = __uint_as_float(lo);
            }
        }
        __syncthreads();

        // S = Q K^T over d (8 k-steps), warp covers 16 q-rows x 32 keys
        float sacc[4][4];
        #pragma unroll
        for (int nt = 0; nt < 4; nt++)
            #pragma unroll
            for (int f = 0; f < 4; f++) sacc[nt][f] = 0.f;

        #pragma unroll
        for (int kk = 0; kk < 8; kk++) {
            int ab = (warp_m * 16 + lr) * PCH + kk * 8 + lc;
            unsigned ah[4], al[4];
            ah[0] = __float_as_uint(Qh[ab]);
            ah[1] = __float_as_uint(Qh[ab + 8 * PCH]);
            ah[2] = __float_as_uint(Qh[ab + 4]);
            ah[3] = __float_as_uint(Qh[ab + 8 * PCH + 4]);
            al[0] = __float_as_uint(Ql[ab]);
            al[1] = __float_as_uint(Ql[ab + 8 * PCH]);
            al[2] = __float_as_uint(Ql[ab + 4]);
            al[3] = __float_as_uint(Ql[ab + 8 * PCH + 4]);
            #pragma unroll
            for (int nt = 0; nt < 4; nt++) {
                int bb = (warp_n * 32 + nt * 8 + lr) * PCH + kk * 8 + lc;
                unsigned bh0 = __float_as_uint(Kh[bb]);
                unsigned bh1 = __float_as_uint(Kh[bb + 4]);
                unsigned bl0 = __float_as_uint(Kl[bb]);
                unsigned bl1 = __float_as_uint(Kl[bb + 4]);
                mma_tf32(sacc[nt], ah, bh0, bh1);
                mma_tf32(sacc[nt], ah, bl0, bl1);
                mma_tf32(sacc[nt], al, bh0, bh1);
            }
        }

        // Causal mask (diagonal tile only)
        if (k0 == q0) {
            #pragma unroll
            for (int nt = 0; nt < 4; nt++) {
                int kc = warp_n * 32 + nt * 8 + 2 * lc;
                if (kc     > row0) sacc[nt][0] = -CUDART_INF_F;
                if (kc + 1 > row0) sacc[nt][1] = -CUDART_INF_F;
                if (kc     > row1) sacc[nt][2] = -CUDART_INF_F;
                if (kc + 1 > row1) sacc[nt][3] = -CUDART_INF_F;
            }
        }

        // Row max: quad-shfl then cross-warp (2 key-halves) via smem
        float tm0 = -CUDART_INF_F, tm1 = -CUDART_INF_F;
        #pragma unroll
        for (int nt = 0; nt < 4; nt++) {
            tm0 = fmaxf(tm0, fmaxf(sacc[nt][0], sacc[nt][1]));
            tm1 = fmaxf(tm1, fmaxf(sacc[nt][2], sacc[nt][3]));
        }
        tm0 = fmaxf(tm0, __shfl_xor_sync(0xffffffffu, tm0, 1));
        tm0 = fmaxf(tm0, __shfl_xor_sync(0xffffffffu, tm0, 2));
        tm1 = fmaxf(tm1, __shfl_xor_sync(0xffffffffu, tm1, 1));
        tm1 = fmaxf(tm1, __shfl_xor_sync(0xffffffffu, tm1, 2));
        if (lc == 0) {
            red0[warp_n * 64 + row0] = tm0;
            red0[warp_n * 64 + row1] = tm1;
        }
        __syncthreads();
        float mx0 = fmaxf(red0[row0], red0[64 + row0]);
        float mx1 = fmaxf(red0[row1], red0[64 + row1]);
        float mn0 = fmaxf(m0s, mx0), mn1 = fmaxf(m1s, mx1);
        float sc0 = __expf(m0s - mn0), sc1 = __expf(m1s - mn1);
        m0s = mn0; m1s = mn1;

        // p = exp(s - m), stage to Ps, row-sum partials
        float rs0 = 0.f, rs1 = 0.f;
        #pragma unroll
        for (int nt = 0; nt < 4; nt++) {
            float p0 = __expf(sacc[nt][0] - mn0);
            float p1 = __expf(sacc[nt][1] - mn0);
            float p2 = __expf(sacc[nt][2] - mn1);
            float p3 = __expf(sacc[nt][3] - mn1);
            rs0 += p0 + p1; rs1 += p2 + p3;
            int pc = warp_n * 32 + nt * 8 + 2 * lc;
            *(float2*)(Ps + row0 * PCH + pc) = make_float2(p0, p1);
            *(float2*)(Ps + row1 * PCH + pc) = make_float2(p2, p3);
        }
        rs0 += __shfl_xor_sync(0xffffffffu, rs0, 1);
        rs0 += __shfl_xor_sync(0xffffffffu, rs0, 2);
        rs1 += __shfl_xor_sync(0xffffffffu, rs1, 1);
        rs1 += __shfl_xor_sync(0xffffffffu, rs1, 2);
        if (lc == 0) {
            red1[warp_n * 64 + row0] = rs0;
            red1[warp_n * 64 + row1] = rs1;
        }
        __syncthreads();
        l0s = l0s * sc0 + red1[row0] + red1[64 + row0];
        l1s = l1s * sc1 + red1[row1] + red1[64 + row1];

        // Rescale O partials
        #pragma unroll
        for (int nt = 0; nt < 8; nt++) {
            oacc[nt][0] *= sc0; oacc[nt][1] *= sc0;
            oacc[nt][2] *= sc1; oacc[nt][3] *= sc1;
        }

        // O += P @ V over the warp's 32-key half (4 k-steps), 8 d-tiles
        #pragma unroll
        for (int kk = 0; kk < 4; kk++) {
            int pb = (warp_m * 16 + lr) * PCH + warp_n * 32 + kk * 8 + lc;
            unsigned ph[4], pl[4];
            split_tf32(Ps[pb],               ph[0], pl[0]);
            split_tf32(Ps[pb + 8 * PCH],     ph[1], pl[1]);
            split_tf32(Ps[pb + 4],           ph[2], pl[2]);
            split_tf32(Ps[pb + 8 * PCH + 4], ph[3], pl[3]);
            #pragma unroll
            for (int nt = 0; nt < 8; nt++) {
                int bb = (nt * 8 + lr) * PCH + warp_n * 32 + kk * 8 + lc;
                unsigned bh0 = __float_as_uint(Vth[bb]);
                unsigned bh1 = __float_as_uint(Vth[bb + 4]);
                unsigned bl0 = __float_as_uint(Vtl[bb]);
                unsigned bl1 = __float_as_uint(Vtl[bb + 4]);
                mma_tf32(oacc[nt], ph, bh0, bh1);
                mma_tf32(oacc[nt], ph, bl0, bl1);
                mma_tf32(oacc[nt], pl, bh0, bh1);
            }
        }
    }

    // Epilogue: sum the two key-half partials, normalize, write out
    __syncthreads();
    if (warp_n == 1) {
        #pragma unroll
        for (int nt = 0; nt < 8; nt++) {
            int c = nt * 8 + 2 * lc;
            *(float2*)(Obuf + row0 * PCH + c) = make_float2(oacc[nt][0], oacc[nt][1]);
            *(float2*)(Obuf + row1 * PCH + c) = make_float2(oacc[nt][2], oacc[nt][3]);
        }
    }
    __syncthreads();
    if (warp_n == 0) {
        float inv0 = 1.f / l0s, inv1 = 1.f / l1s;
        #pragma unroll
        for (int nt = 0; nt < 8; nt++) {
            int c = nt * 8 + 2 * lc;
            float2 p0 = *(const float2*)(Obuf + row0 * PCH + c);
            float2 p1 = *(const float2*)(Obuf + row1 * PCH + c);
            float* o0 = att + (size_t)(b*TT + q0 + row0) * CC + h*DD + c;
            float* o1 = att + (size_t)(b*TT + q0 + row1) * CC + h*DD + c;
            *(float2*)o0 = make_float2((oacc[nt][0] + p0.x) * inv0,
                                       (oacc[nt][1] + p0.y) * inv0);
            *(float2*)o1 = make_float2((oacc[nt][2] + p1.x) * inv1,
                                       (oacc[nt][3] + p1.y) * inv1);
        }
    }
}

// ---------------------------------------------------------------------------
// Launch: QKV GEMM (TC) -> TC flash attention -> proj GEMM (TC)
// ---------------------------------------------------------------------------
extern "C" void kernel_launch(void* const* d_in, const int* in_sizes, int n_in,
                              void* d_out, int out_size)
{
    (void)in_sizes; (void)n_in; (void)out_size;
    const float* x      = (const float*)d_in[0];
    const float* w_qkv  = (const float*)d_in[1];
    const float* w_proj = (const float*)d_in[2];
    float* out = (float*)d_out;

    float* qkv = nullptr;
    float* attb = nullptr;
    cudaGetSymbolAddress((void**)&qkv,  g_qkv);
    cudaGetSymbolAddress((void**)&attb, g_att);

    cudaFuncSetAttribute(attn_kernel,
                         cudaFuncAttributeMaxDynamicSharedMemorySize, ATT_SMEM);

    dim3 g1(F3 / 128, BT / 128);        // (24, 64)
    gemm_nt_tc_kernel<<<g1, 256>>>(x, w_qkv, qkv, BT, F3, CC);

    dim3 g2(TT / 64, BB * HH);          // (32, 64)
    attn_kernel<<<g2, 256, ATT_SMEM>>>(qkv, attb);

    dim3 g3(CC / 128, BT / 128);        // (8, 64)
    gemm_nt_tc_kernel<<<g3, 256>>>(attb, w_proj, out, BT, CC, CC);
}

// round 10
// speedup vs baseline: 1.8735x; 1.8735x over previous
#include <cuda_runtime.h>
#include <cuda_bf16.h>
#include <math_constants.h>

// Problem dims (fixed by the reference)
#define BB 4
#define TT 2048
#define CC 1024
#define HH 16
#define DD 64
#define BT (BB*TT)      // 8192 rows
#define F3 (3*CC)       // 3072 qkv features

// Scratch (allocation-free rule: __device__ globals)
__device__ float g_qkv[BT * F3];   // 100.7 MB
__device__ float g_att[BT * CC];   // 33.6 MB

// ---------------------------------------------------------------------------
// bf16x3 helpers: x = hi + lo (each bf16); D += hi*hi + hi*lo + lo*hi
// gives ~1e-5 relative accuracy (dropped lo*lo ~ 2^-18).
// All smem operand tiles are stored as PACKED bf16 pairs (one 32-bit word =
// two adjacent k elements), exactly the m16n8k16 fragment granularity.
// ---------------------------------------------------------------------------
__device__ __forceinline__ unsigned pack2(float a, float b) {
    __nv_bfloat162 t = __floats2bfloat162_rn(a, b);  // low 16 = a
    return *reinterpret_cast<unsigned*>(&t);
}
__device__ __forceinline__ void split2(float a, float b, unsigned& hi, unsigned& lo) {
    float ah = __bfloat162float(__float2bfloat16(a));
    float bh = __bfloat162float(__float2bfloat16(b));
    hi = pack2(ah, bh);
    lo = pack2(a - ah, b - bh);
}

__device__ __forceinline__ void mma_bf16(float c[4], const unsigned a[4],
                                         unsigned b0, unsigned b1) {
    asm volatile(
        "mma.sync.aligned.m16n8k16.row.col.f32.bf16.bf16.f32 "
        "{%0,%1,%2,%3},{%4,%5,%6,%7},{%8,%9},{%0,%1,%2,%3};"
        : "+f"(c[0]), "+f"(c[1]), "+f"(c[2]), "+f"(c[3])
        : "r"(a[0]), "r"(a[1]), "r"(a[2]), "r"(a[3]), "r"(b0), "r"(b1));
}

// ---------------------------------------------------------------------------
// Tensor-core GEMM (NT): C[m][n] = sum_k A[m][k] * W[n][k]
// Block 128x128, BK=16, 256 threads = 8 warps (2m x 4n), warp tile 64x32.
// bf16 hi/lo pre-split at staging; register-staged LDG prefetch.
// Smem word pitch 20 (16 k -> 8 words + 2 pad words): (20*lr+lc)%32 distinct.
// ---------------------------------------------------------------------------
#define GW 20   // 32-bit words per smem row

__global__ void __launch_bounds__(256, 2) gemm_nt_tc_kernel(
    const float* __restrict__ A, const float* __restrict__ W,
    float* __restrict__ C, int M, int N, int K)
{
    __shared__ unsigned Ah[128 * GW], Al[128 * GW];
    __shared__ unsigned Bh[128 * GW], Bl[128 * GW];

    const int tid    = threadIdx.x;
    const int lane   = tid & 31;
    const int warp   = tid >> 5;
    const int warp_m = warp >> 2;          // 0..1 -> 64-row slab
    const int warp_n = warp & 3;           // 0..3 -> 32-col slab
    const int lr     = lane >> 2;          // 0..7
    const int lc     = lane & 3;           // 0..3
    const int m0     = blockIdx.y * 128;
    const int n0     = blockIdx.x * 128;

    const int ldr = tid >> 2;              // 0..63 loader row
    const int ldk = (tid & 3) << 2;        // k sub-offset (floats)

    float acc[4][4][4];
    #pragma unroll
    for (int i = 0; i < 4; i++)
        #pragma unroll
        for (int j = 0; j < 4; j++)
            #pragma unroll
            for (int f = 0; f < 4; f++) acc[i][j][f] = 0.f;

    float4 ra0, ra1, rb0, rb1;             // register-staged next tile
    auto ldg_tile = [&](int k0) {
        ra0 = *(const float4*)(A + (size_t)(m0 + ldr)      * K + k0 + ldk);
        ra1 = *(const float4*)(A + (size_t)(m0 + ldr + 64) * K + k0 + ldk);
        rb0 = *(const float4*)(W + (size_t)(n0 + ldr)      * K + k0 + ldk);
        rb1 = *(const float4*)(W + (size_t)(n0 + ldr + 64) * K + k0 + ldk);
    };
    auto sts_split = [&]() {
        const float* pa[2] = { (const float*)&ra0, (const float*)&ra1 };
        const float* pb[2] = { (const float*)&rb0, (const float*)&rb1 };
        #pragma unroll
        for (int it = 0; it < 2; it++) {
            int wb = (ldr + it * 64) * GW + (ldk >> 1);
            unsigned hi, lo;
            split2(pa[it][0], pa[it][1], hi, lo);
            Ah[wb] = hi;     Al[wb] = lo;
            split2(pa[it][2], pa[it][3], hi, lo);
            Ah[wb + 1] = hi; Al[wb + 1] = lo;
            split2(pb[it][0], pb[it][1], hi, lo);
            Bh[wb] = hi;     Bl[wb] = lo;
            split2(pb[it][2], pb[it][3], hi, lo);
            Bh[wb + 1] = hi; Bl[wb + 1] = lo;
        }
    };

    const int KT = K >> 4;
    ldg_tile(0);

    for (int kt = 0; kt < KT; kt++) {
        sts_split();
        __syncthreads();
        if (kt + 1 < KT) ldg_tile((kt + 1) << 4);   // overlap with compute

        // one m16n8k16 step covers the whole 16-k tile
        unsigned ah[4][4], al[4][4];
        #pragma unroll
        for (int mt = 0; mt < 4; mt++) {
            int ab = (warp_m * 64 + mt * 16 + lr) * GW + lc;
            ah[mt][0] = Ah[ab];
            ah[mt][1] = Ah[ab + 8 * GW];
            ah[mt][2] = Ah[ab + 4];
            ah[mt][3] = Ah[ab + 8 * GW + 4];
            al[mt][0] = Al[ab];
            al[mt][1] = Al[ab + 8 * GW];
            al[mt][2] = Al[ab + 4];
            al[mt][3] = Al[ab + 8 * GW + 4];
        }
        #pragma unroll
        for (int nt = 0; nt < 4; nt++) {
            int bb = (warp_n * 32 + nt * 8 + lr) * GW + lc;
            unsigned bh0 = Bh[bb], bh1 = Bh[bb + 4];
            unsigned bl0 = Bl[bb], bl1 = Bl[bb + 4];
            #pragma unroll
            for (int mt = 0; mt < 4; mt++) {
                mma_bf16(acc[mt][nt], ah[mt], bh0, bh1);
                mma_bf16(acc[mt][nt], ah[mt], bl0, bl1);
                mma_bf16(acc[mt][nt], al[mt], bh0, bh1);
            }
        }
        __syncthreads();
    }

    #pragma unroll
    for (int mt = 0; mt < 4; mt++) {
        #pragma unroll
        for (int nt = 0; nt < 4; nt++) {
            int r  = m0 + warp_m * 64 + mt * 16 + lr;
            int cc = n0 + warp_n * 32 + nt * 8 + 2 * lc;
            *(float2*)(C + (size_t)r * N + cc)       = make_float2(acc[mt][nt][0], acc[mt][nt][1]);
            *(float2*)(C + (size_t)(r + 8) * N + cc) = make_float2(acc[mt][nt][2], acc[mt][nt][3]);
        }
    }
}

// ---------------------------------------------------------------------------
// Flash attention (causal), bf16x3 tensor cores for S = QK^T and O += P V.
// Block = one (b,h) x 64 query rows. 64 keys/tile, D=64.
// 8 warps: warp_m = warp&3 (16 q-rows), warp_n = warp>>2 (32-key half).
// Smem operand pitch: 36 words (32 data + 4 pad): (36*lr+lc)%32 = 4lr+lc distinct.
// ---------------------------------------------------------------------------
#define AW 36                    // words per row (64 bf16 data + 8 pad)
#define ASZ (64 * AW)            // words per operand tile (2304)
#define PCH 68                   // Ps fp32 pitch
// words: Qh Ql Kh Kl Vth Vtl (6*ASZ) | Ps fp32 | red
#define ATT_SMEM (6 * ASZ * 4 + 64 * PCH * 4 + 256 * 4)   // 73728 B

__global__ void __launch_bounds__(256) attn_kernel(
    const float* __restrict__ qkv, float* __restrict__ att)
{
    extern __shared__ unsigned char smraw[];
    unsigned* Qh  = (unsigned*)smraw;
    unsigned* Ql  = Qh + ASZ;
    unsigned* Kh  = Ql + ASZ;
    unsigned* Kl  = Kh + ASZ;
    unsigned* Vth = Kl + ASZ;          // [d][key] packed key-pairs
    unsigned* Vtl = Vth + ASZ;
    float* Ps   = (float*)(Vtl + ASZ); // [q][key] fp32
    float* red0 = Ps + 64 * PCH;       // [2][64] row max partials
    float* red1 = red0 + 128;          // [2][64] row sum partials
    float* Obuf = (float*)Kh;          // epilogue reuse (Kh+Kl = 18432B >= 17408B)
    __nv_bfloat16* Vthb = (__nv_bfloat16*)Vth;
    __nv_bfloat16* Vtlb = (__nv_bfloat16*)Vtl;

    const int tid    = threadIdx.x;
    const int lane   = tid & 31;
    const int warp   = tid >> 5;
    const int warp_m = warp & 3;        // q-row slab (16 rows)
    const int warp_n = warp >> 2;       // key half (32 keys)
    const int lr     = lane >> 2;
    const int lc     = lane & 3;
    const int bh     = blockIdx.y;
    const int b      = bh >> 4;
    const int h      = bh & 15;
    const int q0     = blockIdx.x * 64;

    const int row0 = warp_m * 16 + lr;
    const int row1 = row0 + 8;

    const float* qbase = qkv + (size_t)(b*TT + q0) * F3 + h*DD;
    const float* kbase = qkv + (size_t)(b*TT) * F3 + CC   + h*DD;
    const float* vbase = qkv + (size_t)(b*TT) * F3 + 2*CC + h*DD;

    // Load Q tile (scaled by 1/sqrt(D)), split to bf16 hi/lo pairs
    {
        const float scale = 0.125f;
        #pragma unroll
        for (int it = 0; it < 4; it++) {
            int fi = tid + it * 256;
            int r  = fi >> 4;
            int d0 = (fi & 15) << 2;
            float4 v = *(const float4*)(qbase + (size_t)r * F3 + d0);
            int wb = r * AW + (d0 >> 1);
            unsigned hi, lo;
            split2(v.x * scale, v.y * scale, hi, lo);
            Qh[wb] = hi;     Ql[wb] = lo;
            split2(v.z * scale, v.w * scale, hi, lo);
            Qh[wb + 1] = hi; Ql[wb + 1] = lo;
        }
    }

    float m0s = -CUDART_INF_F, m1s = -CUDART_INF_F;
    float l0s = 0.f, l1s = 0.f;
    float oacc[8][4];
    #pragma unroll
    for (int nt = 0; nt < 8; nt++)
        #pragma unroll
        for (int f = 0; f < 4; f++) oacc[nt][f] = 0.f;

    const int nkt = (q0 >> 6) + 1;
    for (int kt = 0; kt < nkt; kt++) {
        const int k0 = kt * 64;

        __syncthreads();   // prior tile fully consumed
        // Load K (split, packed) and V (split, transposed scalar stores)
        #pragma unroll
        for (int it = 0; it < 4; it++) {
            int fi = tid + it * 256;
            int r  = fi >> 4;             // key
            int d0 = (fi & 15) << 2;
            float4 kv = *(const float4*)(kbase + (size_t)(k0 + r) * F3 + d0);
            int wb = r * AW + (d0 >> 1);
            unsigned hi, lo;
            split2(kv.x, kv.y, hi, lo);
            Kh[wb] = hi;     Kl[wb] = lo;
            split2(kv.z, kv.w, hi, lo);
            Kh[wb + 1] = hi; Kl[wb + 1] = lo;

            float4 vv4 = *(const float4*)(vbase + (size_t)(k0 + r) * F3 + d0);
            float vv[4] = { vv4.x, vv4.y, vv4.z, vv4.w };
            #pragma unroll
            for (int j = 0; j < 4; j++) {
                __nv_bfloat16 vh = __float2bfloat16(vv[j]);
                Vthb[(d0 + j) * (2*AW) + r] = vh;
                Vtlb[(d0 + j) * (2*AW) + r] =
                    __float2bfloat16(vv[j] - __bfloat162float(vh));
            }
        }
        __syncthreads();

        // S = Q K^T over d (4 k16 steps), warp covers 16 q-rows x 32 keys
        float sacc[4][4];
        #pragma unroll
        for (int nt = 0; nt < 4; nt++)
            #pragma unroll
            for (int f = 0; f < 4; f++) sacc[nt][f] = 0.f;

        #pragma unroll
        for (int kk = 0; kk < 4; kk++) {
            int ab = (warp_m * 16 + lr) * AW + kk * 8 + lc;
            unsigned ah[4], al[4];
            ah[0] = Qh[ab];          ah[1] = Qh[ab + 8 * AW];
            ah[2] = Qh[ab + 4];      ah[3] = Qh[ab + 8 * AW + 4];
            al[0] = Ql[ab];          al[1] = Ql[ab + 8 * AW];
            al[2] = Ql[ab + 4];      al[3] = Ql[ab + 8 * AW + 4];
            #pragma unroll
            for (int nt = 0; nt < 4; nt++) {
                int bb = (warp_n * 32 + nt * 8 + lr) * AW + kk * 8 + lc;
                unsigned bh0 = Kh[bb], bh1 = Kh[bb + 4];
                unsigned bl0 = Kl[bb], bl1 = Kl[bb + 4];
                mma_bf16(sacc[nt], ah, bh0, bh1);
                mma_bf16(sacc[nt], ah, bl0, bl1);
                mma_bf16(sacc[nt], al, bh0, bh1);
            }
        }

        // Causal mask (diagonal tile only)
        if (k0 == q0) {
            #pragma unroll
            for (int nt = 0; nt < 4; nt++) {
                int kc = warp_n * 32 + nt * 8 + 2 * lc;
                if (kc     > row0) sacc[nt][0] = -CUDART_INF_F;
                if (kc + 1 > row0) sacc[nt][1] = -CUDART_INF_F;
                if (kc     > row1) sacc[nt][2] = -CUDART_INF_F;
                if (kc + 1 > row1) sacc[nt][3] = -CUDART_INF_F;
            }
        }

        // Row max: quad-shfl then cross-warp via smem
        float tm0 = -CUDART_INF_F, tm1 = -CUDART_INF_F;
        #pragma unroll
        for (int nt = 0; nt < 4; nt++) {
            tm0 = fmaxf(tm0, fmaxf(sacc[nt][0], sacc[nt][1]));
            tm1 = fmaxf(tm1, fmaxf(sacc[nt][2], sacc[nt][3]));
        }
        tm0 = fmaxf(tm0, __shfl_xor_sync(0xffffffffu, tm0, 1));
        tm0 = fmaxf(tm0, __shfl_xor_sync(0xffffffffu, tm0, 2));
        tm1 = fmaxf(tm1, __shfl_xor_sync(0xffffffffu, tm1, 1));
        tm1 = fmaxf(tm1, __shfl_xor_sync(0xffffffffu, tm1, 2));
        if (lc == 0) {
            red0[warp_n * 64 + row0] = tm0;
            red0[warp_n * 64 + row1] = tm1;
        }
        __syncthreads();
        float mn0 = fmaxf(m0s, fmaxf(red0[row0], red0[64 + row0]));
        float mn1 = fmaxf(m1s, fmaxf(red0[row1], red0[64 + row1]));
        float sc0 = __expf(m0s - mn0), sc1 = __expf(m1s - mn1);
        m0s = mn0; m1s = mn1;

        // p = exp(s - m), stage to Ps, row-sum partials
        float rs0 = 0.f, rs1 = 0.f;
        #pragma unroll
        for (int nt = 0; nt < 4; nt++) {
            float p0 = __expf(sacc[nt][0] - mn0);
            float p1 = __expf(sacc[nt][1] - mn0);
            float p2 = __expf(sacc[nt][2] - mn1);
            float p3 = __expf(sacc[nt][3] - mn1);
            rs0 += p0 + p1; rs1 += p2 + p3;
            int pc = warp_n * 32 + nt * 8 + 2 * lc;
            *(float2*)(Ps + row0 * PCH + pc) = make_float2(p0, p1);
            *(float2*)(Ps + row1 * PCH + pc) = make_float2(p2, p3);
        }
        rs0 += __shfl_xor_sync(0xffffffffu, rs0, 1);
        rs0 += __shfl_xor_sync(0xffffffffu, rs0, 2);
        rs1 += __shfl_xor_sync(0xffffffffu, rs1, 1);
        rs1 += __shfl_xor_sync(0xffffffffu, rs1, 2);
        if (lc == 0) {
            red1[warp_n * 64 + row0] = rs0;
            red1[warp_n * 64 + row1] = rs1;
        }
        __syncthreads();
        l0s = l0s * sc0 + red1[row0] + red1[64 + row0];
        l1s = l1s * sc1 + red1[row1] + red1[64 + row1];

        // Rescale O partials
        #pragma unroll
        for (int nt = 0; nt < 8; nt++) {
            oacc[nt][0] *= sc0; oacc[nt][1] *= sc0;
            oacc[nt][2] *= sc1; oacc[nt][3] *= sc1;
        }

        // O += P @ V over the warp's 32-key half (2 k16 steps), 8 d-tiles
        #pragma unroll
        for (int kk = 0; kk < 2; kk++) {
            int pb0 = row0 * PCH + warp_n * 32 + kk * 16 + 2 * lc;
            int pb1 = row1 * PCH + warp_n * 32 + kk * 16 + 2 * lc;
            unsigned ph[4], pl[4];
            float2 p;
            p = *(const float2*)(Ps + pb0);     split2(p.x, p.y, ph[0], pl[0]);
            p = *(const float2*)(Ps + pb1);     split2(p.x, p.y, ph[1], pl[1]);
            p = *(const float2*)(Ps + pb0 + 8); split2(p.x, p.y, ph[2], pl[2]);
            p = *(const float2*)(Ps + pb1 + 8); split2(p.x, p.y, ph[3], pl[3]);
            #pragma unroll
            for (int nt = 0; nt < 8; nt++) {
                int bb = (nt * 8 + lr) * AW + warp_n * 16 + kk * 8 + lc;
                unsigned bh0 = Vth[bb], bh1 = Vth[bb + 4];
                unsigned bl0 = Vtl[bb], bl1 = Vtl[bb + 4];
                mma_bf16(oacc[nt], ph, bh0, bh1);
                mma_bf16(oacc[nt], ph, bl0, bl1);
                mma_bf16(oacc[nt], pl, bh0, bh1);
            }
        }
    }

    // Epilogue: sum the two key-half partials, normalize, write out
    __syncthreads();
    if (warp_n == 1) {
        #pragma unroll
        for (int nt = 0; nt < 8; nt++) {
            int c = nt * 8 + 2 * lc;
            *(float2*)(Obuf + row0 * PCH + c) = make_float2(oacc[nt][0], oacc[nt][1]);
            *(float2*)(Obuf + row1 * PCH + c) = make_float2(oacc[nt][2], oacc[nt][3]);
        }
    }
    __syncthreads();
    if (warp_n == 0) {
        float inv0 = 1.f / l0s, inv1 = 1.f / l1s;
        #pragma unroll
        for (int nt = 0; nt < 8; nt++) {
            int c = nt * 8 + 2 * lc;
            float2 p0 = *(const float2*)(Obuf + row0 * PCH + c);
            float2 p1 = *(const float2*)(Obuf + row1 * PCH + c);
            float* o0 = att + (size_t)(b*TT + q0 + row0) * CC + h*DD + c;
            float* o1 = att + (size_t)(b*TT + q0 + row1) * CC + h*DD + c;
            *(float2*)o0 = make_float2((oacc[nt][0] + p0.x) * inv0,
                                       (oacc[nt][1] + p0.y) * inv0);
            *(float2*)o1 = make_float2((oacc[nt][2] + p1.x) * inv1,
                                       (oacc[nt][3] + p1.y) * inv1);
        }
    }
}

// ---------------------------------------------------------------------------
// Launch: QKV GEMM (bf16x3 TC) -> TC flash attention -> proj GEMM (bf16x3 TC)
// ---------------------------------------------------------------------------
extern "C" void kernel_launch(void* const* d_in, const int* in_sizes, int n_in,
                              void* d_out, int out_size)
{
    (void)in_sizes; (void)n_in; (void)out_size;
    const float* x      = (const float*)d_in[0];
    const float* w_qkv  = (const float*)d_in[1];
    const float* w_proj = (const float*)d_in[2];
    float* out = (float*)d_out;

    float* qkv = nullptr;
    float* attb = nullptr;
    cudaGetSymbolAddress((void**)&qkv,  g_qkv);
    cudaGetSymbolAddress((void**)&attb, g_att);

    cudaFuncSetAttribute(attn_kernel,
                         cudaFuncAttributeMaxDynamicSharedMemorySize, ATT_SMEM);

    dim3 g1(F3 / 128, BT / 128);        // (24, 64)
    gemm_nt_tc_kernel<<<g1, 256>>>(x, w_qkv, qkv, BT, F3, CC);

    dim3 g2(TT / 64, BB * HH);          // (32, 64)
    attn_kernel<<<g2, 256, ATT_SMEM>>>(qkv, attb);

    dim3 g3(CC / 128, BT / 128);        // (8, 64)
    gemm_nt_tc_kernel<<<g3, 256>>>(attb, w_proj, out, BT, CC, CC);
}

// round 12
// speedup vs baseline: 2.1877x; 1.1677x over previous
#include <cuda_runtime.h>
#include <cuda_bf16.h>
#include <math_constants.h>

// Problem dims (fixed by the reference)
#define BB 4
#define TT 2048
#define CC 1024
#define HH 16
#define DD 64
#define BT (BB*TT)      // 8192 rows
#define F3 (3*CC)       // 3072 qkv features

// Scratch (allocation-free rule: __device__ globals)
__device__ float g_qkv[BT * F3];   // 100.7 MB
__device__ float g_att[BT * CC];   // 33.6 MB

// ---------------------------------------------------------------------------
// bf16x3 helpers: x = hi + lo (each bf16); D += hi*hi + hi*lo + lo*hi
// ---------------------------------------------------------------------------
__device__ __forceinline__ unsigned pack2(float a, float b) {
    __nv_bfloat162 t = __floats2bfloat162_rn(a, b);  // low 16 = a
    return *reinterpret_cast<unsigned*>(&t);
}
__device__ __forceinline__ void split2(float a, float b, unsigned& hi, unsigned& lo) {
    float ah = __bfloat162float(__float2bfloat16(a));
    float bh = __bfloat162float(__float2bfloat16(b));
    hi = pack2(ah, bh);
    lo = pack2(a - ah, b - bh);
}

__device__ __forceinline__ void mma_bf16(float c[4], const unsigned a[4],
                                         unsigned b0, unsigned b1) {
    asm volatile(
        "mma.sync.aligned.m16n8k16.row.col.f32.bf16.bf16.f32 "
        "{%0,%1,%2,%3},{%4,%5,%6,%7},{%8,%9},{%0,%1,%2,%3};"
        : "+f"(c[0]), "+f"(c[1]), "+f"(c[2]), "+f"(c[3])
        : "r"(a[0]), "r"(a[1]), "r"(a[2]), "r"(a[3]), "r"(b0), "r"(b1));
}
#define MMA_BF16 mma_bf16

// ---------------------------------------------------------------------------
// Tensor-core GEMM (NT): C[m][n] = sum_k A[m][k] * W[n][k]
// Block 128x128, BK=16, 256 threads = 8 warps (2m x 4n), warp tile 64x32.
// bf16 hi/lo pre-split at staging; register-staged LDG prefetch.
// ---------------------------------------------------------------------------
#define GW 20   // 32-bit words per smem row

__global__ void __launch_bounds__(256, 2) gemm_nt_tc_kernel(
    const float* __restrict__ A, const float* __restrict__ W,
    float* __restrict__ C, int M, int N, int K)
{
    __shared__ unsigned Ah[128 * GW], Al[128 * GW];
    __shared__ unsigned Bh[128 * GW], Bl[128 * GW];

    const int tid    = threadIdx.x;
    const int lane   = tid & 31;
    const int warp   = tid >> 5;
    const int warp_m = warp >> 2;
    const int warp_n = warp & 3;
    const int lr     = lane >> 2;
    const int lc     = lane & 3;
    const int m0     = blockIdx.y * 128;
    const int n0     = blockIdx.x * 128;

    const int ldr = tid >> 2;
    const int ldk = (tid & 3) << 2;

    float acc[4][4][4];
    #pragma unroll
    for (int i = 0; i < 4; i++)
        #pragma unroll
        for (int j = 0; j < 4; j++)
            #pragma unroll
            for (int f = 0; f < 4; f++) acc[i][j][f] = 0.f;

    float4 ra0, ra1, rb0, rb1;
    auto ldg_tile = [&](int k0) {
        ra0 = *(const float4*)(A + (size_t)(m0 + ldr)      * K + k0 + ldk);
        ra1 = *(const float4*)(A + (size_t)(m0 + ldr + 64) * K + k0 + ldk);
        rb0 = *(const float4*)(W + (size_t)(n0 + ldr)      * K + k0 + ldk);
        rb1 = *(const float4*)(W + (size_t)(n0 + ldr + 64) * K + k0 + ldk);
    };
    auto sts_split = [&]() {
        const float* pa[2] = { (const float*)&ra0, (const float*)&ra1 };
        const float* pb[2] = { (const float*)&rb0, (const float*)&rb1 };
        #pragma unroll
        for (int it = 0; it < 2; it++) {
            int wb = (ldr + it * 64) * GW + (ldk >> 1);
            unsigned hi, lo;
            split2(pa[it][0], pa[it][1], hi, lo);
            Ah[wb] = hi;     Al[wb] = lo;
            split2(pa[it][2], pa[it][3], hi, lo);
            Ah[wb + 1] = hi; Al[wb + 1] = lo;
            split2(pb[it][0], pb[it][1], hi, lo);
            Bh[wb] = hi;     Bl[wb] = lo;
            split2(pb[it][2], pb[it][3], hi, lo);
            Bh[wb + 1] = hi; Bl[wb + 1] = lo;
        }
    };

    const int KT = K >> 4;
    ldg_tile(0);

    for (int kt = 0; kt < KT; kt++) {
        sts_split();
        __syncthreads();
        if (kt + 1 < KT) ldg_tile((kt + 1) << 4);

        unsigned ah[4][4], al[4][4];
        #pragma unroll
        for (int mt = 0; mt < 4; mt++) {
            int ab = (warp_m * 64 + mt * 16 + lr) * GW + lc;
            ah[mt][0] = Ah[ab];
            ah[mt][1] = Ah[ab + 8 * GW];
            ah[mt][2] = Ah[ab + 4];
            ah[mt][3] = Ah[ab + 8 * GW + 4];
            al[mt][0] = Al[ab];
            al[mt][1] = Al[ab + 8 * GW];
            al[mt][2] = Al[ab + 4];
            al[mt][3] = Al[ab + 8 * GW + 4];
        }
        #pragma unroll
        for (int nt = 0; nt < 4; nt++) {
            int bb = (warp_n * 32 + nt * 8 + lr) * GW + lc;
            unsigned bh0 = Bh[bb], bh1 = Bh[bb + 4];
            unsigned bl0 = Bl[bb], bl1 = Bl[bb + 4];
            #pragma unroll
            for (int mt = 0; mt < 4; mt++) {
                MMA_BF16(acc[mt][nt], ah[mt], bh0, bh1);
                MMA_BF16(acc[mt][nt], ah[mt], bl0, bl1);
                MMA_BF16(acc[mt][nt], al[mt], bh0, bh1);
            }
        }
        __syncthreads();
    }

    #pragma unroll
    for (int mt = 0; mt < 4; mt++) {
        #pragma unroll
        for (int nt = 0; nt < 4; nt++) {
            int r  = m0 + warp_m * 64 + mt * 16 + lr;
            int cc = n0 + warp_n * 32 + nt * 8 + 2 * lc;
            *(float2*)(C + (size_t)r * N + cc)       = make_float2(acc[mt][nt][0], acc[mt][nt][1]);
            *(float2*)(C + (size_t)(r + 8) * N + cc) = make_float2(acc[mt][nt][2], acc[mt][nt][3]);
        }
    }
}

// ---------------------------------------------------------------------------
// Flash attention (causal), bf16x3 TC. Block = 128 q-rows; 8 warps, each warp
// owns 16 q-rows x ALL 64 keys of the tile -> warp-local softmax (no cross-
// warp reductions), P kept in registers (S C-frag == PV A-frag layout).
// Q pre-split into smem once per block. Per-warp causal tile skip.
// ---------------------------------------------------------------------------
#define AW 36                     // words per 64-d row (32 data + 4 pad)
#define KV_SZ (64 * AW)           // words per K/V operand tile
#define Q_SZ  (128 * AW)          // words per Q operand (128 rows)
#define ATT_SMEM ((2 * Q_SZ + 4 * KV_SZ) * 4)   // 73728 B

__global__ void __launch_bounds__(256, 2) attn_kernel(
    const float* __restrict__ qkv, float* __restrict__ att)
{
    extern __shared__ unsigned smw[];
    unsigned* Qh  = smw;               // [128][AW] packed d-pairs
    unsigned* Ql  = Qh + Q_SZ;
    unsigned* Kh  = Ql + Q_SZ;         // [key][d-pairs]
    unsigned* Kl  = Kh + KV_SZ;
    unsigned* Vth = Kl + KV_SZ;        // [d][key-pairs]
    unsigned* Vtl = Vth + KV_SZ;
    __nv_bfloat16* Vthb = (__nv_bfloat16*)Vth;
    __nv_bfloat16* Vtlb = (__nv_bfloat16*)Vtl;

    const int tid  = threadIdx.x;
    const int lane = tid & 31;
    const int warp = tid >> 5;         // 0..7 -> 16 q-rows each
    const int g    = lane >> 2;        // 0..7 row-in-group
    const int tig  = lane & 3;         // 0..3
    const int bh   = blockIdx.y;
    const int b    = bh >> 4;
    const int h    = bh & 15;
    const int q0   = blockIdx.x * 128;

    const int qrow = q0 + warp * 16 + g;   // global q row (and +8)

    const float* qbase = qkv + (size_t)(b*TT + q0) * F3 + h*DD;
    const float* kbase = qkv + (size_t)(b*TT) * F3 + CC   + h*DD;
    const float* vbase = qkv + (size_t)(b*TT) * F3 + 2*CC + h*DD;

    // Stage Q (scaled by 1/8), split hi/lo, packed d-pairs
    {
        const float scale = 0.125f;
        #pragma unroll
        for (int it = 0; it < 8; it++) {
            int fi = tid + it * 256;
            int r  = fi >> 4;
            int d0 = (fi & 15) << 2;
            float4 v = *(const float4*)(qbase + (size_t)r * F3 + d0);
            int wb = r * AW + (d0 >> 1);
            unsigned hi, lo;
            split2(v.x * scale, v.y * scale, hi, lo);
            Qh[wb] = hi;     Ql[wb] = lo;
            split2(v.z * scale, v.w * scale, hi, lo);
            Qh[wb + 1] = hi; Ql[wb + 1] = lo;
        }
    }

    float m0s = -CUDART_INF_F, m1s = -CUDART_INF_F;
    float l0s = 0.f, l1s = 0.f;
    float oacc[8][4];
    #pragma unroll
    for (int nt = 0; nt < 8; nt++)
        #pragma unroll
        for (int f = 0; f < 4; f++) oacc[nt][f] = 0.f;

    const int nkt = (q0 >> 6) + 2;
    for (int kt = 0; kt < nkt; kt++) {
        const int k0 = kt * 64;

        __syncthreads();   // prior tile consumed (and Q staged on iter 0)
        #pragma unroll
        for (int it = 0; it < 4; it++) {
            int fi = tid + it * 256;
            int r  = fi >> 4;             // key
            int d0 = (fi & 15) << 2;
            float4 kv = *(const float4*)(kbase + (size_t)(k0 + r) * F3 + d0);
            int wb = r * AW + (d0 >> 1);
            unsigned hi, lo;
            split2(kv.x, kv.y, hi, lo);
            Kh[wb] = hi;     Kl[wb] = lo;
            split2(kv.z, kv.w, hi, lo);
            Kh[wb + 1] = hi; Kl[wb + 1] = lo;

            float4 vv4 = *(const float4*)(vbase + (size_t)(k0 + r) * F3 + d0);
            float vv[4] = { vv4.x, vv4.y, vv4.z, vv4.w };
            #pragma unroll
            for (int j = 0; j < 4; j++) {
                __nv_bfloat16 vh = __float2bfloat16(vv[j]);
                Vthb[(d0 + j) * (2*AW) + r] = vh;
                Vtlb[(d0 + j) * (2*AW) + r] =
                    __float2bfloat16(vv[j] - __bfloat162float(vh));
            }
        }
        __syncthreads();

        // Warp-uniform causal tile skip (all keys in tile > all warp rows)
        if (k0 > q0 + warp * 16 + 15) continue;

        // S = Q K^T : 16 q-rows x 64 keys (8 n-tiles x 4 k16-steps x 3 passes)
        float sacc[8][4];
        #pragma unroll
        for (int nt = 0; nt < 8; nt++)
            #pragma unroll
            for (int f = 0; f < 4; f++) sacc[nt][f] = 0.f;

        const int qb = (warp * 16 + g) * AW;
        #pragma unroll
        for (int kk = 0; kk < 4; kk++) {
            int ab = qb + kk * 8 + tig;
            unsigned ah[4], al[4];
            ah[0] = Qh[ab];          ah[1] = Qh[ab + 8 * AW];
            ah[2] = Qh[ab + 4];      ah[3] = Qh[ab + 8 * AW + 4];
            al[0] = Ql[ab];          al[1] = Ql[ab + 8 * AW];
            al[2] = Ql[ab + 4];      al[3] = Ql[ab + 8 * AW + 4];
            #pragma unroll
            for (int nt = 0; nt < 8; nt++) {
                int bb = (nt * 8 + g) * AW + kk * 8 + tig;
                unsigned bh0 = Kh[bb], bh1 = Kh[bb + 4];
                unsigned bl0 = Kl[bb], bl1 = Kl[bb + 4];
                MMA_BF16(sacc[nt], ah, bh0, bh1);
                MMA_BF16(sacc[nt], ah, bl0, bl1);
                MMA_BF16(sacc[nt], al, bh0, bh1);
            }
        }

        // Causal mask where tile overlaps the warp's diagonal
        if (k0 + 63 > q0 + warp * 16) {
            #pragma unroll
            for (int nt = 0; nt < 8; nt++) {
                int key = k0 + nt * 8 + 2 * tig;
                if (key     > qrow)     sacc[nt][0] = -CUDART_INF_F;
                if (key + 1 > qrow)     sacc[nt][1] = -CUDART_INF_F;
                if (key     > qrow + 8) sacc[nt][2] = -CUDART_INF_F;
                if (key + 1 > qrow + 8) sacc[nt][3] = -CUDART_INF_F;
            }
        }

        // Warp-local online softmax (rows live in quads: shfl xor 1,2)
        float tm0 = -CUDART_INF_F, tm1 = -CUDART_INF_F;
        #pragma unroll
        for (int nt = 0; nt < 8; nt++) {
            tm0 = fmaxf(tm0, fmaxf(sacc[nt][0], sacc[nt][1]));
            tm1 = fmaxf(tm1, fmaxf(sacc[nt][2], sacc[nt][3]));
        }
        tm0 = fmaxf(tm0, __shfl_xor_sync(0xffffffffu, tm0, 1));
        tm0 = fmaxf(tm0, __shfl_xor_sync(0xffffffffu, tm0, 2));
        tm1 = fmaxf(tm1, __shfl_xor_sync(0xffffffffu, tm1, 1));
        tm1 = fmaxf(tm1, __shfl_xor_sync(0xffffffffu, tm1, 2));
        float mn0 = fmaxf(m0s, tm0), mn1 = fmaxf(m1s, tm1);
        float sc0 = __expf(m0s - mn0), sc1 = __expf(m1s - mn1);
        m0s = mn0; m1s = mn1;

        float rs0 = 0.f, rs1 = 0.f;
        #pragma unroll
        for (int nt = 0; nt < 8; nt++) {
            sacc[nt][0] = __expf(sacc[nt][0] - mn0);
            sacc[nt][1] = __expf(sacc[nt][1] - mn0);
            sacc[nt][2] = __expf(sacc[nt][2] - mn1);
            sacc[nt][3] = __expf(sacc[nt][3] - mn1);
            rs0 += sacc[nt][0] + sacc[nt][1];
            rs1 += sacc[nt][2] + sacc[nt][3];
        }
        rs0 += __shfl_xor_sync(0xffffffffu, rs0, 1);
        rs0 += __shfl_xor_sync(0xffffffffu, rs0, 2);
        rs1 += __shfl_xor_sync(0xffffffffu, rs1, 1);
        rs1 += __shfl_xor_sync(0xffffffffu, rs1, 2);
        l0s = l0s * sc0 + rs0;
        l1s = l1s * sc1 + rs1;

        #pragma unroll
        for (int nt = 0; nt < 8; nt++) {
            oacc[nt][0] *= sc0; oacc[nt][1] *= sc0;
            oacc[nt][2] *= sc1; oacc[nt][3] *= sc1;
        }

        // O += P V : P straight from registers (S C-frag == PV A-frag layout)
        #pragma unroll
        for (int kk = 0; kk < 4; kk++) {
            unsigned ph[4], pl[4];
            split2(sacc[2*kk][0],   sacc[2*kk][1],   ph[0], pl[0]);
            split2(sacc[2*kk][2],   sacc[2*kk][3],   ph[1], pl[1]);
            split2(sacc[2*kk+1][0], sacc[2*kk+1][1], ph[2], pl[2]);
            split2(sacc[2*kk+1][2], sacc[2*kk+1][3], ph[3], pl[3]);
            #pragma unroll
            for (int nt = 0; nt < 8; nt++) {
                int bb = (nt * 8 + g) * AW + kk * 8 + tig;
                unsigned vh0 = Vth[bb], vh1 = Vth[bb + 4];
                unsigned vl0 = Vtl[bb], vl1 = Vtl[bb + 4];
                MMA_BF16(oacc[nt], ph, vh0, vh1);
                MMA_BF16(oacc[nt], ph, vl0, vl1);
                MMA_BF16(oacc[nt], pl, vh0, vh1);
            }
        }
    }

    // Epilogue: normalize, write [B,T,C] head-interleaved
    float inv0 = 1.f / l0s, inv1 = 1.f / l1s;
    #pragma unroll
    for (int nt = 0; nt < 8; nt++) {
        int c = h*DD + nt * 8 + 2 * tig;
        float* o0 = att + (size_t)(b*TT + qrow) * CC + c;
        float* o1 = att + (size_t)(b*TT + qrow + 8) * CC + c;
        *(float2*)o0 = make_float2(oacc[nt][0] * inv0, oacc[nt][1] * inv0);
        *(float2*)o1 = make_float2(oacc[nt][2] * inv1, oacc[nt][3] * inv1);
    }
}

// ---------------------------------------------------------------------------
// Launch: QKV GEMM -> TC flash attention (128q blocks) -> proj GEMM
// ---------------------------------------------------------------------------
extern "C" void kernel_launch(void* const* d_in, const int* in_sizes, int n_in,
                              void* d_out, int out_size)
{
    (void)in_sizes; (void)n_in; (void)out_size;
    const float* x      = (const float*)d_in[0];
    const float* w_qkv  = (const float*)d_in[1];
    const float* w_proj = (const float*)d_in[2];
    float* out = (float*)d_out;

    float* qkv = nullptr;
    float* attb = nullptr;
    cudaGetSymbolAddress((void**)&qkv,  g_qkv);
    cudaGetSymbolAddress((void**)&attb, g_att);

    cudaFuncSetAttribute(attn_kernel,
                         cudaFuncAttributeMaxDynamicSharedMemorySize, ATT_SMEM);

    dim3 g1(F3 / 128, BT / 128);        // (24, 64)
    gemm_nt_tc_kernel<<<g1, 256>>>(x, w_qkv, qkv, BT, F3, CC);

    dim3 g2(TT / 128, BB * HH);         // (16, 64)
    attn_kernel<<<g2, 256, ATT_SMEM>>>(qkv, attb);

    dim3 g3(CC / 128, BT / 128);        // (8, 64)
    gemm_nt_tc_kernel<<<g3, 256>>>(attb, w_proj, out, BT, CC, CC);
}